// round 1
// baseline (speedup 1.0000x reference)
#include <cuda_runtime.h>

#define NTOK 8192
#define DDIM 1024
#define HDIM 2048

// ---------------- scratch (static device globals; no runtime allocation) ---
__device__ float g_t1[NTOK * DDIM];
__device__ float g_keys[NTOK * DDIM];
__device__ float g_values[NTOK * DDIM];
__device__ float g_queries[NTOK * DDIM];
__device__ float g_retr[NTOK * DDIM];
__device__ float g_pred[NTOK * DDIM];
__device__ float g_hk[NTOK * HDIM];
__device__ float g_ak[NTOK * HDIM];
__device__ float g_da[NTOK * HDIM];   // also used as a_q before backward
__device__ float g_g0[HDIM * DDIM];
__device__ float g_g1[DDIM * HDIM];
__device__ float g_xmean[4 * DDIM];
__device__ float g_gpart[3 * 32];
__device__ float g_gates[3];

static __device__ __forceinline__ float sigf(float x) {
    return 1.0f / (1.0f + __expf(-x));
}
static __device__ __forceinline__ float siluf(float x) {
    return x * sigf(x);
}

// ---------------- SGEMM: C[M,N] = A op B, fp32, tiles 128x128x16 ----------
// AMODE 0: A is K-contiguous, element A[m*lda + k]   (x @ W^T style)
// AMODE 1: A is M-contiguous, element A[k*lda + m]   (A^T style, K = rows)
// BMODE 0: B is K-contiguous, element B[n*ldb + k]   (W^T style)
// BMODE 1: B is N-contiguous, element B[k*ldb + n]   (plain style)
// EPI 0: none, 1: silu
#define BKT 16

template <int AMODE, int BMODE, int EPI>
__global__ __launch_bounds__(256, 2) void sgemm_kernel(
    const float* __restrict__ A, const float* __restrict__ B,
    float* __restrict__ C, int M, int N, int K, int lda, int ldb)
{
    __shared__ float As[BKT][132];
    __shared__ float Bs[BKT][132];
    const int col0 = blockIdx.x * 128;
    const int row0 = blockIdx.y * 128;
    const int t = threadIdx.x;
    const int tx = t & 15;
    const int ty = t >> 4;

    float acc[8][8];
#pragma unroll
    for (int i = 0; i < 8; i++)
#pragma unroll
        for (int j = 0; j < 8; j++) acc[i][j] = 0.0f;

    for (int k0 = 0; k0 < K; k0 += BKT) {
        if (AMODE == 0) {
#pragma unroll
            for (int it = 0; it < 2; it++) {
                int r = (t >> 2) + it * 64;
                int kq = (t & 3) * 4;
                float4 v = *(const float4*)&A[(size_t)(row0 + r) * lda + k0 + kq];
                As[kq + 0][r] = v.x; As[kq + 1][r] = v.y;
                As[kq + 2][r] = v.z; As[kq + 3][r] = v.w;
            }
        } else {
#pragma unroll
            for (int it = 0; it < 2; it++) {
                int k = (t >> 5) + it * 8;
                int mq = (t & 31) * 4;
                *(float4*)&As[k][mq] =
                    *(const float4*)&A[(size_t)(k0 + k) * lda + row0 + mq];
            }
        }
        if (BMODE == 0) {
#pragma unroll
            for (int it = 0; it < 2; it++) {
                int r = (t >> 2) + it * 64;
                int kq = (t & 3) * 4;
                float4 v = *(const float4*)&B[(size_t)(col0 + r) * ldb + k0 + kq];
                Bs[kq + 0][r] = v.x; Bs[kq + 1][r] = v.y;
                Bs[kq + 2][r] = v.z; Bs[kq + 3][r] = v.w;
            }
        } else {
#pragma unroll
            for (int it = 0; it < 2; it++) {
                int k = (t >> 5) + it * 8;
                int nq = (t & 31) * 4;
                *(float4*)&Bs[k][nq] =
                    *(const float4*)&B[(size_t)(k0 + k) * ldb + col0 + nq];
            }
        }
        __syncthreads();
#pragma unroll
        for (int k = 0; k < BKT; k++) {
            float a[8], b[8];
            *(float4*)&a[0] = *(const float4*)&As[k][ty * 4];
            *(float4*)&a[4] = *(const float4*)&As[k][64 + ty * 4];
            *(float4*)&b[0] = *(const float4*)&Bs[k][tx * 4];
            *(float4*)&b[4] = *(const float4*)&Bs[k][64 + tx * 4];
#pragma unroll
            for (int i = 0; i < 8; i++)
#pragma unroll
                for (int j = 0; j < 8; j++)
                    acc[i][j] = fmaf(a[i], b[j], acc[i][j]);
        }
        __syncthreads();
    }

#pragma unroll
    for (int ih = 0; ih < 2; ih++)
#pragma unroll
        for (int ii = 0; ii < 4; ii++) {
            int i = ih * 4 + ii;
            size_t r = (size_t)(row0 + ih * 64 + ty * 4 + ii);
#pragma unroll
            for (int jh = 0; jh < 2; jh++) {
                float4 v;
                v.x = acc[i][jh * 4 + 0];
                v.y = acc[i][jh * 4 + 1];
                v.z = acc[i][jh * 4 + 2];
                v.w = acc[i][jh * 4 + 3];
                if (EPI == 1) {
                    v.x = siluf(v.x); v.y = siluf(v.y);
                    v.z = siluf(v.z); v.w = siluf(v.w);
                }
                *(float4*)&C[r * (size_t)N + col0 + jh * 64 + tx * 4] = v;
            }
        }
}

// ---------------- elementwise / reduction kernels --------------------------

// L2 normalize rows of length 1024 (in place). grid = rows, block = 256.
__global__ void l2norm_kernel(float* __restrict__ x)
{
    float4* p = (float4*)(x + (size_t)blockIdx.x * DDIM);
    int t = threadIdx.x;
    float4 v = p[t];
    float ss = v.x * v.x + v.y * v.y + v.z * v.z + v.w * v.w;
    __shared__ float red[8];
#pragma unroll
    for (int o = 16; o; o >>= 1) ss += __shfl_xor_sync(~0u, ss, o);
    if ((t & 31) == 0) red[t >> 5] = ss;
    __syncthreads();
    if (t < 8) {
        float s2 = red[t];
#pragma unroll
        for (int o = 4; o; o >>= 1) s2 += __shfl_xor_sync(0xffu, s2, o);
        if (t == 0) red[0] = s2;
    }
    __syncthreads();
    float scale = 1.0f / fmaxf(sqrtf(red[0]), 1e-12f);
    v.x *= scale; v.y *= scale; v.z *= scale; v.w *= scale;
    p[t] = v;
}

__global__ void silu_kernel(const float4* __restrict__ src, float4* __restrict__ dst)
{
    int i = blockIdx.x * 256 + threadIdx.x;
    float4 v = src[i];
    v.x = siluf(v.x); v.y = siluf(v.y); v.z = siluf(v.z); v.w = siluf(v.w);
    dst[i] = v;
}

// pred -> dpred = 2*(pred - values)/(N*D), in place
__global__ void dpred_kernel(float4* __restrict__ pred, const float4* __restrict__ vals)
{
    int i = blockIdx.x * 256 + threadIdx.x;
    const float c = 2.0f / (float)(NTOK * DDIM);
    float4 p = pred[i], v = vals[i];
    p.x = (p.x - v.x) * c; p.y = (p.y - v.y) * c;
    p.z = (p.z - v.z) * c; p.w = (p.w - v.w) * c;
    pred[i] = p;
}

// da *= silu'(h),  silu'(h) = s*(1 + h*(1-s))
__global__ void dh_kernel(float4* __restrict__ da, const float4* __restrict__ h)
{
    int i = blockIdx.x * 256 + threadIdx.x;
    float4 d = da[i], hv = h[i];
    float s;
    s = sigf(hv.x); d.x *= s * (1.0f + hv.x * (1.0f - s));
    s = sigf(hv.y); d.y *= s * (1.0f + hv.y * (1.0f - s));
    s = sigf(hv.z); d.z *= s * (1.0f + hv.z * (1.0f - s));
    s = sigf(hv.w); d.w *= s * (1.0f + hv.w * (1.0f - s));
    da[i] = d;
}

// x_mean[b,d] = mean over S. grid = 16, block = 256.
__global__ void xmean_kernel(const float* __restrict__ x, float* __restrict__ xm)
{
    int idx = blockIdx.x * 256 + threadIdx.x;   // 0..4095
    int b = idx >> 10, d = idx & 1023;
    const float* p = x + ((size_t)b * 2048) * DDIM + d;
    float s = 0.0f;
#pragma unroll 8
    for (int ss = 0; ss < 2048; ss++) s += p[(size_t)ss * DDIM];
    xm[idx] = s * (1.0f / 2048.0f);
}

// partial sums of sigmoid(xm @ W^T + b) per gate. grid = (32, 3), block = 128.
__global__ void gate_partial_kernel(
    const float* __restrict__ xm,
    const float* __restrict__ gdw, const float* __restrict__ gdb,
    const float* __restrict__ glw, const float* __restrict__ glb,
    const float* __restrict__ gmw, const float* __restrict__ gmb,
    float* __restrict__ part)
{
    int g = blockIdx.y;
    const float* W = (g == 0) ? gdw : (g == 1) ? glw : gmw;
    const float* bias = (g == 0) ? gdb : (g == 1) ? glb : gmb;
    int warp = threadIdx.x >> 5, lane = threadIdx.x & 31;
    float acc = 0.0f;
#pragma unroll
    for (int jj = 0; jj < 8; jj++) {
        int j = blockIdx.x * 32 + warp * 8 + jj;
        const float* wr = W + (size_t)j * DDIM;
        float bj = bias[j];
        for (int bb = 0; bb < 4; bb++) {
            const float* xr = xm + bb * DDIM;
            float s = 0.0f;
            for (int d = lane; d < DDIM; d += 32) s += xr[d] * wr[d];
#pragma unroll
            for (int o = 16; o; o >>= 1) s += __shfl_xor_sync(~0u, s, o);
            if (lane == 0) acc += sigf(s + bj);
        }
    }
    __shared__ float sred[4];
    if (lane == 0) sred[warp] = acc;
    __syncthreads();
    if (threadIdx.x == 0)
        part[g * 32 + blockIdx.x] = sred[0] + sred[1] + sred[2] + sred[3];
}

// finalize gates: mean over 4*1024 sigmoid values. <<<1, 96>>>
__global__ void gate_final_kernel(const float* __restrict__ part, float* __restrict__ gates)
{
    int t = threadIdx.x;
    if (t < 96) {
        int g = t >> 5, lane = t & 31;
        float v = part[g * 32 + lane];
#pragma unroll
        for (int o = 16; o; o >>= 1) v += __shfl_xor_sync(~0u, v, o);
        if (lane == 0) gates[g] = v * (1.0f / 4096.0f);
    }
}

// weight/momentum update, writes new_w0,new_w1,new_m0,new_m1 into d_out
__global__ void update_kernel(
    const float4* __restrict__ w0, const float4* __restrict__ w1,
    const float4* __restrict__ m0, const float4* __restrict__ m1,
    const float4* __restrict__ gg0, const float4* __restrict__ gg1,
    const float* __restrict__ gates, float4* __restrict__ out4)
{
    const int HD4 = HDIM * DDIM / 4;            // 524288
    int i = blockIdx.x * 256 + threadIdx.x;     // 0 .. 2*HD4-1
    float alpha = gates[0], theta = gates[1], eta = gates[2];
    float oma = 1.0f - alpha;
    // float4 offsets in out: out=0, w0=2097152, w1=2621440, m0=3145728, m1=3670016
    if (i < HD4) {
        float4 g = gg0[i], m = m0[i], w = w0[i], nm, nw;
        nm.x = eta * m.x - theta * g.x; nw.x = oma * w.x + nm.x;
        nm.y = eta * m.y - theta * g.y; nw.y = oma * w.y + nm.y;
        nm.z = eta * m.z - theta * g.z; nw.z = oma * w.z + nm.z;
        nm.w = eta * m.w - theta * g.w; nw.w = oma * w.w + nm.w;
        out4[2097152 + i] = nw;
        out4[3145728 + i] = nm;
    } else {
        int j = i - HD4;
        float4 g = gg1[j], m = m1[j], w = w1[j], nm, nw;
        nm.x = eta * m.x - theta * g.x; nw.x = oma * w.x + nm.x;
        nm.y = eta * m.y - theta * g.y; nw.y = oma * w.y + nm.y;
        nm.z = eta * m.z - theta * g.z; nw.z = oma * w.z + nm.z;
        nm.w = eta * m.w - theta * g.w; nw.w = oma * w.w + nm.w;
        out4[2621440 + j] = nw;
        out4[3670016 + j] = nm;
    }
}

// ---------------- host ------------------------------------------------------

extern "C" void kernel_launch(void* const* d_in, const int* in_sizes, int n_in,
                              void* d_out, int out_size)
{
    (void)in_sizes; (void)n_in; (void)out_size;
    const float* x      = (const float*)d_in[0];
    const float* kp_w1  = (const float*)d_in[1];
    const float* kp_w2  = (const float*)d_in[2];
    const float* vp_w1  = (const float*)d_in[3];
    const float* vp_w2  = (const float*)d_in[4];
    const float* qp_w1  = (const float*)d_in[5];
    const float* qp_w2  = (const float*)d_in[6];
    const float* gd_w   = (const float*)d_in[7];
    const float* gd_b   = (const float*)d_in[8];
    const float* gl_w   = (const float*)d_in[9];
    const float* gl_b   = (const float*)d_in[10];
    const float* gm_w   = (const float*)d_in[11];
    const float* gm_b   = (const float*)d_in[12];
    const float* mem_w0 = (const float*)d_in[13];
    const float* mem_w1 = (const float*)d_in[14];
    const float* mom0   = (const float*)d_in[15];
    const float* mom1   = (const float*)d_in[16];
    const float* out_w  = (const float*)d_in[17];
    float* out = (float*)d_out;

    float *t1, *keys, *values, *queries, *retr, *pred, *hk, *ak, *da;
    float *gg0, *gg1, *xmean, *gpart, *gates;
    cudaGetSymbolAddress((void**)&t1, g_t1);
    cudaGetSymbolAddress((void**)&keys, g_keys);
    cudaGetSymbolAddress((void**)&values, g_values);
    cudaGetSymbolAddress((void**)&queries, g_queries);
    cudaGetSymbolAddress((void**)&retr, g_retr);
    cudaGetSymbolAddress((void**)&pred, g_pred);
    cudaGetSymbolAddress((void**)&hk, g_hk);
    cudaGetSymbolAddress((void**)&ak, g_ak);
    cudaGetSymbolAddress((void**)&da, g_da);
    cudaGetSymbolAddress((void**)&gg0, g_g0);
    cudaGetSymbolAddress((void**)&gg1, g_g1);
    cudaGetSymbolAddress((void**)&xmean, g_xmean);
    cudaGetSymbolAddress((void**)&gpart, g_gpart);
    cudaGetSymbolAddress((void**)&gates, g_gates);

    // ---- gate scalars (independent of GEMM chain) ----
    xmean_kernel<<<16, 256>>>(x, xmean);
    gate_partial_kernel<<<dim3(32, 3), 128>>>(xmean, gd_w, gd_b, gl_w, gl_b,
                                              gm_w, gm_b, gpart);
    gate_final_kernel<<<1, 96>>>(gpart, gates);

    // ---- projections: silu(silu(x @ w1^T) @ w2^T) ----
    dim3 gND(DDIM / 128, NTOK / 128);   // (8, 64)
    dim3 gNH(HDIM / 128, NTOK / 128);   // (16, 64)
    sgemm_kernel<0, 0, 1><<<gND, 256>>>(x, kp_w1, t1, NTOK, DDIM, DDIM, DDIM, DDIM);
    sgemm_kernel<0, 0, 1><<<gND, 256>>>(t1, kp_w2, keys, NTOK, DDIM, DDIM, DDIM, DDIM);
    sgemm_kernel<0, 0, 1><<<gND, 256>>>(x, vp_w1, t1, NTOK, DDIM, DDIM, DDIM, DDIM);
    sgemm_kernel<0, 0, 1><<<gND, 256>>>(t1, vp_w2, values, NTOK, DDIM, DDIM, DDIM, DDIM);
    sgemm_kernel<0, 0, 1><<<gND, 256>>>(x, qp_w1, t1, NTOK, DDIM, DDIM, DDIM, DDIM);
    sgemm_kernel<0, 0, 1><<<gND, 256>>>(t1, qp_w2, queries, NTOK, DDIM, DDIM, DDIM, DDIM);
    l2norm_kernel<<<NTOK, 256>>>(keys);
    l2norm_kernel<<<NTOK, 256>>>(queries);

    // ---- memory read: retrieved = silu(q @ w0^T) @ w1^T ; out = retr @ out_w^T
    sgemm_kernel<0, 0, 1><<<gNH, 256>>>(queries, mem_w0, da, NTOK, HDIM, DDIM, DDIM, DDIM);
    sgemm_kernel<0, 0, 0><<<gND, 256>>>(da, mem_w1, retr, NTOK, DDIM, HDIM, HDIM, HDIM);
    sgemm_kernel<0, 0, 0><<<gND, 256>>>(retr, out_w, out, NTOK, DDIM, DDIM, DDIM, DDIM);

    // ---- loss forward on keys ----
    sgemm_kernel<0, 0, 0><<<gNH, 256>>>(keys, mem_w0, hk, NTOK, HDIM, DDIM, DDIM, DDIM);
    silu_kernel<<<NTOK * HDIM / 1024, 256>>>((const float4*)hk, (float4*)ak);
    sgemm_kernel<0, 0, 0><<<gND, 256>>>(ak, mem_w1, pred, NTOK, DDIM, HDIM, HDIM, HDIM);
    dpred_kernel<<<NTOK * DDIM / 1024, 256>>>((float4*)pred, (const float4*)values);

    // ---- backward ----
    // g1[D,H] = dpred^T @ a_k   (TN, K = 8192)
    sgemm_kernel<1, 1, 0><<<dim3(HDIM / 128, DDIM / 128), 256>>>(
        pred, ak, gg1, DDIM, HDIM, NTOK, DDIM, HDIM);
    // da[N,H] = dpred @ w1      (NN)
    sgemm_kernel<0, 1, 0><<<gNH, 256>>>(pred, mem_w1, da, NTOK, HDIM, DDIM, DDIM, HDIM);
    dh_kernel<<<NTOK * HDIM / 1024, 256>>>((float4*)da, (const float4*)hk);
    // g0[H,D] = dh^T @ keys     (TN, K = 8192)
    sgemm_kernel<1, 1, 0><<<dim3(DDIM / 128, HDIM / 128), 256>>>(
        da, keys, gg0, HDIM, DDIM, NTOK, HDIM, DDIM);

    // ---- weight / momentum update ----
    update_kernel<<<2 * HDIM * DDIM / 4 / 256, 256>>>(
        (const float4*)mem_w0, (const float4*)mem_w1,
        (const float4*)mom0, (const float4*)mom1,
        (const float4*)gg0, (const float4*)gg1, gates, (float4*)out);
}

// round 3
// speedup vs baseline: 2.1584x; 2.1584x over previous
#include <cuda_runtime.h>
#include <cuda_bf16.h>
#include <cstdint>

#define NTOK 8192
#define DDIM 1024
#define HDIM 2048
#define MI 1048576ULL

typedef __nv_bfloat16 bf16;

// ===================== scratch (static device globals) ======================
__device__ float g_keys[NTOK * DDIM];
__device__ float g_values[NTOK * DDIM];
__device__ float g_queries[NTOK * DDIM];
__device__ float g_hk[NTOK * HDIM];
__device__ float g_ak[NTOK * HDIM];
__device__ float g_pred[NTOK * DDIM];
__device__ float g_da[NTOK * HDIM];
__device__ float g_g0[HDIM * DDIM];
__device__ float g_g1[DDIM * HDIM];
__device__ float g_xmean[4 * DDIM];
__device__ float g_gpart[3 * 32];
__device__ float g_gates[3];

__device__ bf16 g_bfh[141 * MI];
__device__ bf16 g_bfl[141 * MI];

// offsets (elements) inside g_bfh/g_bfl
#define O_X    (0 * MI)
#define O_T1   (8 * MI)
#define O_KEY  (16 * MI)
#define O_KEYT (24 * MI)
#define O_Q    (32 * MI)
#define O_AQ   (40 * MI)   // 16Mi
#define O_RETR (56 * MI)
#define O_AK   (64 * MI)   // 16Mi
#define O_AKT  (80 * MI)   // 16Mi
#define O_DP   (96 * MI)
#define O_DPT  (104 * MI)
#define O_DHT  (112 * MI)  // 16Mi
#define O_KP1  (128 * MI)
#define O_KP2  (129 * MI)
#define O_VP1  (130 * MI)
#define O_VP2  (131 * MI)
#define O_QP1  (132 * MI)
#define O_QP2  (133 * MI)
#define O_OW   (134 * MI)
#define O_M0   (135 * MI)  // 2Mi
#define O_M1   (137 * MI)  // 2Mi
#define O_M1T  (139 * MI)  // 2Mi

// ===================== small helpers =======================================
static __device__ __forceinline__ float sigf(float x) {
    return 1.0f / (1.0f + __expf(-x));
}
static __device__ __forceinline__ float siluf(float x) { return x * sigf(x); }

static __device__ __forceinline__ void split1(float v, bf16& h, bf16& l) {
    h = __float2bfloat16(v);
    l = __float2bfloat16(v - __bfloat162float(h));
}
static __device__ __forceinline__ unsigned packu(bf16 a, bf16 b) {
    unsigned short x = *(unsigned short*)&a, y = *(unsigned short*)&b;
    return (unsigned)x | ((unsigned)y << 16);
}
static __device__ __forceinline__ uint32_t smem_u32(const void* p) {
    uint32_t a;
    asm("{ .reg .u64 t; cvta.to.shared.u64 t, %1; cvt.u32.u64 %0, t; }"
        : "=r"(a) : "l"(p));
    return a;
}

// cp.async / ldmatrix / mma wrappers (all sm_80-compatible)
static __device__ __forceinline__ void cp16(uint32_t s, const void* g) {
    asm volatile("cp.async.ca.shared.global [%0], [%1], 16;" :: "r"(s), "l"(g));
}
static __device__ __forceinline__ void cp_commit() {
    asm volatile("cp.async.commit_group;" ::: "memory");
}
template <int N>
static __device__ __forceinline__ void cp_wait() {
    asm volatile("cp.async.wait_group %0;" :: "n"(N) : "memory");
}
static __device__ __forceinline__ void ldm4(uint32_t a, uint32_t& r0, uint32_t& r1,
                                            uint32_t& r2, uint32_t& r3) {
    asm volatile("ldmatrix.sync.aligned.m8n8.x4.shared.b16 {%0,%1,%2,%3}, [%4];"
                 : "=r"(r0), "=r"(r1), "=r"(r2), "=r"(r3) : "r"(a));
}
static __device__ __forceinline__ void mma16816(float* c, const uint32_t* a,
                                                const uint32_t* b) {
    asm volatile(
        "mma.sync.aligned.m16n8k16.row.col.f32.bf16.bf16.f32 "
        "{%0,%1,%2,%3}, {%4,%5,%6,%7}, {%8,%9}, {%0,%1,%2,%3};"
        : "+f"(c[0]), "+f"(c[1]), "+f"(c[2]), "+f"(c[3])
        : "r"(a[0]), "r"(a[1]), "r"(a[2]), "r"(a[3]), "r"(b[0]), "r"(b[1]));
}

// ===================== mma.sync GEMM =======================================
// C[M,N] = sum_k A[m,k]*B[n,k]; A/B bf16 hi+lo, row-major K-contiguous.
// CTA tile 128x128x32, 8 warps (warp 64x32), bf16x3 split, 3-stage cp.async.
#define BKG 32
#define RSB 80                        // smem row stride bytes (32 bf16 + 8 pad)
#define TILE_B (128 * RSB)            // 10240
#define STAGE_B (4 * TILE_B)          // 40960
#define NSTAGE 3
#define GSMEM (NSTAGE * STAGE_B)      // 122880

template <int EPI, bool WF32, bool WBF>
__global__ __launch_bounds__(256, 1)
void mma_gemm(const bf16* __restrict__ Ahi, const bf16* __restrict__ Alo,
              const bf16* __restrict__ Bhi, const bf16* __restrict__ Blo,
              float* __restrict__ C, bf16* __restrict__ Chi, bf16* __restrict__ Clo,
              int M, int N, int K)
{
    extern __shared__ char sm[];
    uint32_t sb = smem_u32(sm);
    const int t = threadIdx.x, lane = t & 31, wid = t >> 5;
    const int row0 = blockIdx.y * 128, col0 = blockIdx.x * 128;

    const bf16* gA0 = Ahi + (size_t)row0 * K;
    const bf16* gA1 = Alo + (size_t)row0 * K;
    const bf16* gB0 = Bhi + (size_t)col0 * K;
    const bf16* gB1 = Blo + (size_t)col0 * K;

    const int r_ld = t >> 2, kc = t & 3;

    auto issue = [&](int s) {
        int k0 = s * BKG;
        uint32_t dst = sb + (s % NSTAGE) * STAGE_B;
        const bf16* srcs[4] = {gA0, gA1, gB0, gB1};
#pragma unroll
        for (int q = 0; q < 4; q++) {
            const bf16* base = srcs[q] + k0 + kc * 8;
            uint32_t d = dst + q * TILE_B + kc * 16;
            cp16(d + r_ld * RSB, base + (size_t)r_ld * K);
            cp16(d + (64 + r_ld) * RSB, base + (size_t)(64 + r_ld) * K);
        }
        cp_commit();
    };

    const int wm = wid & 1, wn = wid >> 1;
    float acc[4][4][4];
#pragma unroll
    for (int i = 0; i < 4; i++)
#pragma unroll
        for (int j = 0; j < 4; j++)
#pragma unroll
            for (int r = 0; r < 4; r++) acc[i][j][r] = 0.0f;

    const int arow = wm * 64 + (lane & 15);
    const int acolh = (lane >> 4) * 16;
    const int brow = wn * 32 + (lane & 7) + ((lane >> 4) << 3);
    const int bcolh = ((lane >> 3) & 1) * 16;

    const int S = K / BKG;
    issue(0);
    issue(1);
    for (int s = 0; s < S; s++) {
        if (s + 1 < S) cp_wait<1>(); else cp_wait<0>();
        __syncthreads();
        if (s + 2 < S) issue(s + 2);

        uint32_t st = sb + (s % NSTAGE) * STAGE_B;
        uint32_t aAh = st, aAl = st + TILE_B;
        uint32_t aBh = st + 2 * TILE_B, aBl = st + 3 * TILE_B;
#pragma unroll
        for (int kb = 0; kb < 2; kb++) {
            uint32_t ah[4][4], al[4][4], bh[4][2], bl[4][2];
#pragma unroll
            for (int mi = 0; mi < 4; mi++) {
                uint32_t off = (uint32_t)(arow + mi * 16) * RSB + kb * 32 + acolh;
                ldm4(aAh + off, ah[mi][0], ah[mi][1], ah[mi][2], ah[mi][3]);
                ldm4(aAl + off, al[mi][0], al[mi][1], al[mi][2], al[mi][3]);
            }
#pragma unroll
            for (int jp = 0; jp < 2; jp++) {
                uint32_t off = (uint32_t)(brow + jp * 16) * RSB + kb * 32 + bcolh;
                uint32_t r0, r1, r2, r3;
                ldm4(aBh + off, r0, r1, r2, r3);
                bh[jp * 2][0] = r0; bh[jp * 2][1] = r1;
                bh[jp * 2 + 1][0] = r2; bh[jp * 2 + 1][1] = r3;
                ldm4(aBl + off, r0, r1, r2, r3);
                bl[jp * 2][0] = r0; bl[jp * 2][1] = r1;
                bl[jp * 2 + 1][0] = r2; bl[jp * 2 + 1][1] = r3;
            }
#pragma unroll
            for (int mi = 0; mi < 4; mi++)
#pragma unroll
                for (int nj = 0; nj < 4; nj++) {
                    mma16816(acc[mi][nj], ah[mi], bh[nj]);
                    mma16816(acc[mi][nj], ah[mi], bl[nj]);
                    mma16816(acc[mi][nj], al[mi], bh[nj]);
                }
        }
        __syncthreads();
    }

    // epilogue
    const int grow = lane >> 2, gc2 = (lane & 3) * 2;
#pragma unroll
    for (int mi = 0; mi < 4; mi++) {
#pragma unroll
        for (int nj = 0; nj < 4; nj++) {
            int col = col0 + wn * 32 + nj * 8 + gc2;
#pragma unroll
            for (int h = 0; h < 2; h++) {
                size_t row = (size_t)(row0 + wm * 64 + mi * 16 + grow + h * 8);
                float v0 = acc[mi][nj][h * 2], v1 = acc[mi][nj][h * 2 + 1];
                if (EPI == 1) { v0 = siluf(v0); v1 = siluf(v1); }
                if (WF32)
                    *(float2*)&C[row * (size_t)N + col] = make_float2(v0, v1);
                if (WBF) {
                    bf16 h0, l0, h1, l1;
                    split1(v0, h0, l0);
                    split1(v1, h1, l1);
                    *(unsigned*)&Chi[row * (size_t)N + col] = packu(h0, h1);
                    *(unsigned*)&Clo[row * (size_t)N + col] = packu(l0, l1);
                }
            }
        }
    }
}

// ===================== conversion / elementwise kernels ====================

__global__ void conv_kernel(const float4* __restrict__ src,
                            bf16* __restrict__ hi, bf16* __restrict__ lo)
{
    int i = blockIdx.x * 256 + threadIdx.x;
    float4 v = src[i];
    bf16 h0, l0, h1, l1, h2, l2, h3, l3;
    split1(v.x, h0, l0); split1(v.y, h1, l1);
    split1(v.z, h2, l2); split1(v.w, h3, l3);
    ((uint2*)hi)[i] = make_uint2(packu(h0, h1), packu(h2, h3));
    ((uint2*)lo)[i] = make_uint2(packu(l0, l1), packu(l2, l3));
}

// transpose + convert: src fp32 [R][C] -> dst hi/lo bf16 [C][R]
__global__ void trans_conv_kernel(const float* __restrict__ src,
                                  bf16* __restrict__ dhi, bf16* __restrict__ dlo,
                                  int R, int C)
{
    __shared__ float tile[32][33];
    int tx = threadIdx.x, ty = threadIdx.y;   // 32 x 8
    int r0 = blockIdx.y * 32, c0 = blockIdx.x * 32;
#pragma unroll
    for (int i = 0; i < 4; i++)
        tile[ty + i * 8][tx] = src[(size_t)(r0 + ty + i * 8) * C + c0 + tx];
    __syncthreads();
#pragma unroll
    for (int i = 0; i < 4; i++) {
        float v = tile[tx][ty + i * 8];
        size_t o = (size_t)(c0 + ty + i * 8) * R + r0 + tx;
        bf16 h, l; split1(v, h, l);
        dhi[o] = h; dlo[o] = l;
    }
}

template <bool WF32>
__global__ void l2norm_kernel(float* __restrict__ x,
                              bf16* __restrict__ hi, bf16* __restrict__ lo)
{
    float4* p = (float4*)(x + (size_t)blockIdx.x * DDIM);
    int t = threadIdx.x;
    float4 v = p[t];
    float ss = v.x * v.x + v.y * v.y + v.z * v.z + v.w * v.w;
    __shared__ float red[8];
#pragma unroll
    for (int o = 16; o; o >>= 1) ss += __shfl_xor_sync(~0u, ss, o);
    if ((t & 31) == 0) red[t >> 5] = ss;
    __syncthreads();
    if (t < 8) {
        float s2 = red[t];
#pragma unroll
        for (int o = 4; o; o >>= 1) s2 += __shfl_xor_sync(0xffu, s2, o);
        if (t == 0) red[0] = s2;
    }
    __syncthreads();
    float scale = 1.0f / fmaxf(sqrtf(red[0]), 1e-12f);
    v.x *= scale; v.y *= scale; v.z *= scale; v.w *= scale;
    if (WF32) p[t] = v;
    size_t i = (size_t)blockIdx.x * 256 + t;
    bf16 h0, l0, h1, l1, h2, l2, h3, l3;
    split1(v.x, h0, l0); split1(v.y, h1, l1);
    split1(v.z, h2, l2); split1(v.w, h3, l3);
    ((uint2*)hi)[i] = make_uint2(packu(h0, h1), packu(h2, h3));
    ((uint2*)lo)[i] = make_uint2(packu(l0, l1), packu(l2, l3));
}

__global__ void silu_conv_kernel(const float4* __restrict__ src, float4* __restrict__ dst,
                                 bf16* __restrict__ hi, bf16* __restrict__ lo)
{
    int i = blockIdx.x * 256 + threadIdx.x;
    float4 v = src[i];
    v.x = siluf(v.x); v.y = siluf(v.y); v.z = siluf(v.z); v.w = siluf(v.w);
    dst[i] = v;
    bf16 h0, l0, h1, l1, h2, l2, h3, l3;
    split1(v.x, h0, l0); split1(v.y, h1, l1);
    split1(v.z, h2, l2); split1(v.w, h3, l3);
    ((uint2*)hi)[i] = make_uint2(packu(h0, h1), packu(h2, h3));
    ((uint2*)lo)[i] = make_uint2(packu(l0, l1), packu(l2, l3));
}

__global__ void dpred_conv_kernel(float4* __restrict__ pred, const float4* __restrict__ vals,
                                  bf16* __restrict__ hi, bf16* __restrict__ lo)
{
    int i = blockIdx.x * 256 + threadIdx.x;
    const float c = 2.0f / (float)((size_t)NTOK * DDIM);
    float4 p = pred[i], v = vals[i];
    p.x = (p.x - v.x) * c; p.y = (p.y - v.y) * c;
    p.z = (p.z - v.z) * c; p.w = (p.w - v.w) * c;
    pred[i] = p;
    bf16 h0, l0, h1, l1, h2, l2, h3, l3;
    split1(p.x, h0, l0); split1(p.y, h1, l1);
    split1(p.z, h2, l2); split1(p.w, h3, l3);
    ((uint2*)hi)[i] = make_uint2(packu(h0, h1), packu(h2, h3));
    ((uint2*)lo)[i] = make_uint2(packu(l0, l1), packu(l2, l3));
}

__global__ void dh_kernel(float4* __restrict__ da, const float4* __restrict__ h)
{
    int i = blockIdx.x * 256 + threadIdx.x;
    float4 d = da[i], hv = h[i];
    float s;
    s = sigf(hv.x); d.x *= s * (1.0f + hv.x * (1.0f - s));
    s = sigf(hv.y); d.y *= s * (1.0f + hv.y * (1.0f - s));
    s = sigf(hv.z); d.z *= s * (1.0f + hv.z * (1.0f - s));
    s = sigf(hv.w); d.w *= s * (1.0f + hv.w * (1.0f - s));
    da[i] = d;
}

__global__ void xmean_kernel(const float* __restrict__ x, float* __restrict__ xm)
{
    int idx = blockIdx.x * 256 + threadIdx.x;
    int b = idx >> 10, d = idx & 1023;
    const float* p = x + ((size_t)b * 2048) * DDIM + d;
    float s = 0.0f;
#pragma unroll 8
    for (int ss = 0; ss < 2048; ss++) s += p[(size_t)ss * DDIM];
    xm[idx] = s * (1.0f / 2048.0f);
}

__global__ void gate_partial_kernel(
    const float* __restrict__ xm,
    const float* __restrict__ gdw, const float* __restrict__ gdb,
    const float* __restrict__ glw, const float* __restrict__ glb,
    const float* __restrict__ gmw, const float* __restrict__ gmb,
    float* __restrict__ part)
{
    int g = blockIdx.y;
    const float* W = (g == 0) ? gdw : (g == 1) ? glw : gmw;
    const float* bias = (g == 0) ? gdb : (g == 1) ? glb : gmb;
    int warp = threadIdx.x >> 5, lane = threadIdx.x & 31;
    float acc = 0.0f;
#pragma unroll
    for (int jj = 0; jj < 8; jj++) {
        int j = blockIdx.x * 32 + warp * 8 + jj;
        const float* wr = W + (size_t)j * DDIM;
        float bj = bias[j];
        for (int bb = 0; bb < 4; bb++) {
            const float* xr = xm + bb * DDIM;
            float s = 0.0f;
            for (int d = lane; d < DDIM; d += 32) s += xr[d] * wr[d];
#pragma unroll
            for (int o = 16; o; o >>= 1) s += __shfl_xor_sync(~0u, s, o);
            if (lane == 0) acc += sigf(s + bj);
        }
    }
    __shared__ float sred[4];
    if (lane == 0) sred[warp] = acc;
    __syncthreads();
    if (threadIdx.x == 0)
        part[g * 32 + blockIdx.x] = sred[0] + sred[1] + sred[2] + sred[3];
}

__global__ void gate_final_kernel(const float* __restrict__ part, float* __restrict__ gates)
{
    int t = threadIdx.x;
    if (t < 96) {
        int g = t >> 5, lane = t & 31;
        float v = part[g * 32 + lane];
#pragma unroll
        for (int o = 16; o; o >>= 1) v += __shfl_xor_sync(~0u, v, o);
        if (lane == 0) gates[g] = v * (1.0f / 4096.0f);
    }
}

__global__ void update_kernel(
    const float4* __restrict__ w0, const float4* __restrict__ w1,
    const float4* __restrict__ m0, const float4* __restrict__ m1,
    const float4* __restrict__ gg0, const float4* __restrict__ gg1,
    const float* __restrict__ gates, float4* __restrict__ out4)
{
    const int HD4 = HDIM * DDIM / 4;
    int i = blockIdx.x * 256 + threadIdx.x;
    float alpha = gates[0], theta = gates[1], eta = gates[2];
    float oma = 1.0f - alpha;
    if (i < HD4) {
        float4 g = gg0[i], m = m0[i], w = w0[i], nm, nw;
        nm.x = eta * m.x - theta * g.x; nw.x = oma * w.x + nm.x;
        nm.y = eta * m.y - theta * g.y; nw.y = oma * w.y + nm.y;
        nm.z = eta * m.z - theta * g.z; nw.z = oma * w.z + nm.z;
        nm.w = eta * m.w - theta * g.w; nw.w = oma * w.w + nm.w;
        out4[2097152 + i] = nw;
        out4[3145728 + i] = nm;
    } else {
        int j = i - HD4;
        float4 g = gg1[j], m = m1[j], w = w1[j], nm, nw;
        nm.x = eta * m.x - theta * g.x; nw.x = oma * w.x + nm.x;
        nm.y = eta * m.y - theta * g.y; nw.y = oma * w.y + nm.y;
        nm.z = eta * m.z - theta * g.z; nw.z = oma * w.z + nm.z;
        nm.w = eta * m.w - theta * g.w; nw.w = oma * w.w + nm.w;
        out4[2621440 + j] = nw;
        out4[3670016 + j] = nm;
    }
}

// ===================== host ================================================

extern "C" void kernel_launch(void* const* d_in, const int* in_sizes, int n_in,
                              void* d_out, int out_size)
{
    (void)in_sizes; (void)n_in; (void)out_size;
    const float* x      = (const float*)d_in[0];
    const float* kp_w1  = (const float*)d_in[1];
    const float* kp_w2  = (const float*)d_in[2];
    const float* vp_w1  = (const float*)d_in[3];
    const float* vp_w2  = (const float*)d_in[4];
    const float* qp_w1  = (const float*)d_in[5];
    const float* qp_w2  = (const float*)d_in[6];
    const float* gd_w   = (const float*)d_in[7];
    const float* gd_b   = (const float*)d_in[8];
    const float* gl_w   = (const float*)d_in[9];
    const float* gl_b   = (const float*)d_in[10];
    const float* gm_w   = (const float*)d_in[11];
    const float* gm_b   = (const float*)d_in[12];
    const float* mem_w0 = (const float*)d_in[13];
    const float* mem_w1 = (const float*)d_in[14];
    const float* mom0   = (const float*)d_in[15];
    const float* mom1   = (const float*)d_in[16];
    const float* out_w  = (const float*)d_in[17];
    float* out = (float*)d_out;

    float *keys, *values, *queries, *hk, *ak, *pred, *da, *gg0, *gg1;
    float *xmean, *gpart, *gates;
    bf16 *bh, *bl;
    cudaGetSymbolAddress((void**)&keys, g_keys);
    cudaGetSymbolAddress((void**)&values, g_values);
    cudaGetSymbolAddress((void**)&queries, g_queries);
    cudaGetSymbolAddress((void**)&hk, g_hk);
    cudaGetSymbolAddress((void**)&ak, g_ak);
    cudaGetSymbolAddress((void**)&pred, g_pred);
    cudaGetSymbolAddress((void**)&da, g_da);
    cudaGetSymbolAddress((void**)&gg0, g_g0);
    cudaGetSymbolAddress((void**)&gg1, g_g1);
    cudaGetSymbolAddress((void**)&xmean, g_xmean);
    cudaGetSymbolAddress((void**)&gpart, g_gpart);
    cudaGetSymbolAddress((void**)&gates, g_gates);
    cudaGetSymbolAddress((void**)&bh, g_bfh);
    cudaGetSymbolAddress((void**)&bl, g_bfl);

    cudaFuncSetAttribute(mma_gemm<1, false, true>, cudaFuncAttributeMaxDynamicSharedMemorySize, GSMEM);
    cudaFuncSetAttribute(mma_gemm<1, true, false>, cudaFuncAttributeMaxDynamicSharedMemorySize, GSMEM);
    cudaFuncSetAttribute(mma_gemm<0, false, true>, cudaFuncAttributeMaxDynamicSharedMemorySize, GSMEM);
    cudaFuncSetAttribute(mma_gemm<0, true, false>, cudaFuncAttributeMaxDynamicSharedMemorySize, GSMEM);

    // ---- gates (independent chain) ----
    xmean_kernel<<<16, 256>>>(x, xmean);
    gate_partial_kernel<<<dim3(32, 3), 128>>>(xmean, gd_w, gd_b, gl_w, gl_b,
                                              gm_w, gm_b, gpart);
    gate_final_kernel<<<1, 96>>>(gpart, gates);

    // ---- conversions of inputs ----
    conv_kernel<<<8192, 256>>>((const float4*)x, bh + O_X, bl + O_X);
    conv_kernel<<<1024, 256>>>((const float4*)kp_w1, bh + O_KP1, bl + O_KP1);
    conv_kernel<<<1024, 256>>>((const float4*)kp_w2, bh + O_KP2, bl + O_KP2);
    conv_kernel<<<1024, 256>>>((const float4*)vp_w1, bh + O_VP1, bl + O_VP1);
    conv_kernel<<<1024, 256>>>((const float4*)vp_w2, bh + O_VP2, bl + O_VP2);
    conv_kernel<<<1024, 256>>>((const float4*)qp_w1, bh + O_QP1, bl + O_QP1);
    conv_kernel<<<1024, 256>>>((const float4*)qp_w2, bh + O_QP2, bl + O_QP2);
    conv_kernel<<<1024, 256>>>((const float4*)out_w, bh + O_OW, bl + O_OW);
    conv_kernel<<<2048, 256>>>((const float4*)mem_w0, bh + O_M0, bl + O_M0);
    conv_kernel<<<2048, 256>>>((const float4*)mem_w1, bh + O_M1, bl + O_M1);
    trans_conv_kernel<<<dim3(HDIM / 32, DDIM / 32), dim3(32, 8)>>>(
        mem_w1, bh + O_M1T, bl + O_M1T, DDIM, HDIM);   // w1T [H][D]

    dim3 blk(256);
    dim3 gND(DDIM / 128, NTOK / 128);   // (8, 64)
    dim3 gNH(HDIM / 128, NTOK / 128);   // (16, 64)

    // ---- K projection ----
    mma_gemm<1, false, true><<<gND, blk, GSMEM>>>(
        bh + O_X, bl + O_X, bh + O_KP1, bl + O_KP1,
        nullptr, bh + O_T1, bl + O_T1, NTOK, DDIM, DDIM);
    mma_gemm<1, true, false><<<gND, blk, GSMEM>>>(
        bh + O_T1, bl + O_T1, bh + O_KP2, bl + O_KP2,
        keys, nullptr, nullptr, NTOK, DDIM, DDIM);
    l2norm_kernel<true><<<NTOK, 256>>>(keys, bh + O_KEY, bl + O_KEY);
    trans_conv_kernel<<<dim3(DDIM / 32, NTOK / 32), dim3(32, 8)>>>(
        keys, bh + O_KEYT, bl + O_KEYT, NTOK, DDIM);   // keysT [D][NTOK]

    // ---- V projection ----
    mma_gemm<1, false, true><<<gND, blk, GSMEM>>>(
        bh + O_X, bl + O_X, bh + O_VP1, bl + O_VP1,
        nullptr, bh + O_T1, bl + O_T1, NTOK, DDIM, DDIM);
    mma_gemm<1, true, false><<<gND, blk, GSMEM>>>(
        bh + O_T1, bl + O_T1, bh + O_VP2, bl + O_VP2,
        values, nullptr, nullptr, NTOK, DDIM, DDIM);

    // ---- Q projection ----
    mma_gemm<1, false, true><<<gND, blk, GSMEM>>>(
        bh + O_X, bl + O_X, bh + O_QP1, bl + O_QP1,
        nullptr, bh + O_T1, bl + O_T1, NTOK, DDIM, DDIM);
    mma_gemm<1, true, false><<<gND, blk, GSMEM>>>(
        bh + O_T1, bl + O_T1, bh + O_QP2, bl + O_QP2,
        queries, nullptr, nullptr, NTOK, DDIM, DDIM);
    l2norm_kernel<false><<<NTOK, 256>>>(queries, bh + O_Q, bl + O_Q);

    // ---- memory read: retr = silu(q @ w0^T) @ w1^T ; out = retr @ out_w^T ----
    mma_gemm<1, false, true><<<gNH, blk, GSMEM>>>(
        bh + O_Q, bl + O_Q, bh + O_M0, bl + O_M0,
        nullptr, bh + O_AQ, bl + O_AQ, NTOK, HDIM, DDIM);
    mma_gemm<0, false, true><<<gND, blk, GSMEM>>>(
        bh + O_AQ, bl + O_AQ, bh + O_M1, bl + O_M1,
        nullptr, bh + O_RETR, bl + O_RETR, NTOK, DDIM, HDIM);
    mma_gemm<0, true, false><<<gND, blk, GSMEM>>>(
        bh + O_RETR, bl + O_RETR, bh + O_OW, bl + O_OW,
        out, nullptr, nullptr, NTOK, DDIM, DDIM);

    // ---- loss forward on keys ----
    mma_gemm<0, true, false><<<gNH, blk, GSMEM>>>(
        bh + O_KEY, bl + O_KEY, bh + O_M0, bl + O_M0,
        hk, nullptr, nullptr, NTOK, HDIM, DDIM);
    silu_conv_kernel<<<NTOK * HDIM / 1024, 256>>>(
        (const float4*)hk, (float4*)ak, bh + O_AK, bl + O_AK);
    trans_conv_kernel<<<dim3(HDIM / 32, NTOK / 32), dim3(32, 8)>>>(
        ak, bh + O_AKT, bl + O_AKT, NTOK, HDIM);       // akT [H][NTOK]
    mma_gemm<0, true, false><<<gND, blk, GSMEM>>>(
        bh + O_AK, bl + O_AK, bh + O_M1, bl + O_M1,
        pred, nullptr, nullptr, NTOK, DDIM, HDIM);
    dpred_conv_kernel<<<NTOK * DDIM / 1024, 256>>>(
        (float4*)pred, (const float4*)values, bh + O_DP, bl + O_DP);
    trans_conv_kernel<<<dim3(DDIM / 32, NTOK / 32), dim3(32, 8)>>>(
        pred, bh + O_DPT, bl + O_DPT, NTOK, DDIM);     // dpredT [D][NTOK]

    // ---- backward ----
    // g1[D,H] = dpredT . akT   (K = NTOK)
    mma_gemm<0, true, false><<<dim3(HDIM / 128, DDIM / 128), blk, GSMEM>>>(
        bh + O_DPT, bl + O_DPT, bh + O_AKT, bl + O_AKT,
        gg1, nullptr, nullptr, DDIM, HDIM, NTOK);
    // da[N,H] = dpred . w1T    (K = D)
    mma_gemm<0, true, false><<<gNH, blk, GSMEM>>>(
        bh + O_DP, bl + O_DP, bh + O_M1T, bl + O_M1T,
        da, nullptr, nullptr, NTOK, HDIM, DDIM);
    dh_kernel<<<NTOK * HDIM / 1024, 256>>>((float4*)da, (const float4*)hk);
    trans_conv_kernel<<<dim3(HDIM / 32, NTOK / 32), dim3(32, 8)>>>(
        da, bh + O_DHT, bl + O_DHT, NTOK, HDIM);       // dhT [H][NTOK]
    // g0[H,D] = dhT . keysT    (K = NTOK)
    mma_gemm<0, true, false><<<dim3(DDIM / 128, HDIM / 128), blk, GSMEM>>>(
        bh + O_DHT, bl + O_DHT, bh + O_KEYT, bl + O_KEYT,
        gg0, nullptr, nullptr, HDIM, DDIM, NTOK);

    // ---- weight / momentum update ----
    update_kernel<<<2 * HDIM * DDIM / 4 / 256, 256>>>(
        (const float4*)mem_w0, (const float4*)mem_w1,
        (const float4*)mom0, (const float4*)mom1,
        (const float4*)gg0, (const float4*)gg1, gates, (float4*)out);
}

// round 4
// speedup vs baseline: 2.3974x; 1.1107x over previous
#include <cuda_runtime.h>
#include <cuda_bf16.h>
#include <cstdint>

#define NTOK 8192
#define DDIM 1024
#define HDIM 2048
#define MI 1048576ULL

typedef __nv_bfloat16 bf16;

// ===================== scratch (static device globals) ======================
__device__ float g_keys[NTOK * DDIM];
__device__ float g_values[NTOK * DDIM];
__device__ float g_queries[NTOK * DDIM];
__device__ float g_hk[NTOK * HDIM];
__device__ float g_pred[NTOK * DDIM];
__device__ float g_da[NTOK * HDIM];
__device__ float g_g0[HDIM * DDIM];
__device__ float g_g1[DDIM * HDIM];
__device__ float g_xmean[4 * DDIM];
__device__ float g_gpart[3 * 32];
__device__ float g_gates[3];

__device__ bf16 g_bfh[141 * MI];
__device__ bf16 g_bfl[141 * MI];

// offsets (elements) inside g_bfh/g_bfl
#define O_X    (0 * MI)
#define O_T1   (8 * MI)
#define O_KEY  (16 * MI)
#define O_KEYT (24 * MI)
#define O_Q    (32 * MI)
#define O_AQ   (40 * MI)   // 16Mi
#define O_RETR (56 * MI)
#define O_AK   (64 * MI)   // 16Mi
#define O_AKT  (80 * MI)   // 16Mi
#define O_DP   (96 * MI)
#define O_DPT  (104 * MI)
#define O_DHT  (112 * MI)  // 16Mi
#define O_KP1  (128 * MI)
#define O_KP2  (129 * MI)
#define O_VP1  (130 * MI)
#define O_VP2  (131 * MI)
#define O_QP1  (132 * MI)
#define O_QP2  (133 * MI)
#define O_OW   (134 * MI)
#define O_M0   (135 * MI)  // 2Mi
#define O_M1   (137 * MI)  // 2Mi
#define O_M1T  (139 * MI)  // 2Mi

// ===================== small helpers =======================================
static __device__ __forceinline__ float sigf(float x) {
    return 1.0f / (1.0f + __expf(-x));
}
static __device__ __forceinline__ float siluf(float x) { return x * sigf(x); }

static __device__ __forceinline__ void split1(float v, bf16& h, bf16& l) {
    h = __float2bfloat16(v);
    l = __float2bfloat16(v - __bfloat162float(h));
}
static __device__ __forceinline__ unsigned packu(bf16 a, bf16 b) {
    unsigned short x = *(unsigned short*)&a, y = *(unsigned short*)&b;
    return (unsigned)x | ((unsigned)y << 16);
}
static __device__ __forceinline__ uint32_t smem_u32(const void* p) {
    uint32_t a;
    asm("{ .reg .u64 t; cvta.to.shared.u64 t, %1; cvt.u32.u64 %0, t; }"
        : "=r"(a) : "l"(p));
    return a;
}

// cp.async / ldmatrix / mma wrappers (sm_80-compatible)
static __device__ __forceinline__ void cp16(uint32_t s, const void* g) {
    asm volatile("cp.async.cg.shared.global [%0], [%1], 16;" :: "r"(s), "l"(g));
}
static __device__ __forceinline__ void cp_commit() {
    asm volatile("cp.async.commit_group;" ::: "memory");
}
template <int N>
static __device__ __forceinline__ void cp_wait() {
    asm volatile("cp.async.wait_group %0;" :: "n"(N) : "memory");
}
static __device__ __forceinline__ void ldm4(uint32_t a, uint32_t& r0, uint32_t& r1,
                                            uint32_t& r2, uint32_t& r3) {
    asm volatile("ldmatrix.sync.aligned.m8n8.x4.shared.b16 {%0,%1,%2,%3}, [%4];"
                 : "=r"(r0), "=r"(r1), "=r"(r2), "=r"(r3) : "r"(a));
}
static __device__ __forceinline__ void mma16816(float* c, const uint32_t* a,
                                                const uint32_t* b) {
    asm volatile(
        "mma.sync.aligned.m16n8k16.row.col.f32.bf16.bf16.f32 "
        "{%0,%1,%2,%3}, {%4,%5,%6,%7}, {%8,%9}, {%0,%1,%2,%3};"
        : "+f"(c[0]), "+f"(c[1]), "+f"(c[2]), "+f"(c[3])
        : "r"(a[0]), "r"(a[1]), "r"(a[2]), "r"(a[3]), "r"(b[0]), "r"(b[1]));
}

// ===================== mma.sync GEMM =======================================
// C[M,N] = sum_k A[m,k]*B[n,k]; A/B bf16 hi+lo, row-major K-contiguous.
// CTA tile 128x128x64, 8 warps (warp 64x32), bf16x3 split, 3-stage cp.async,
// single __syncthreads per stage.
#define BKG 64
#define RSB 144                       // 64 bf16 (128B) + 16B pad
#define TILE_B (128 * RSB)            // 18432
#define STAGE_B (4 * TILE_B)          // 73728
#define NSTAGE 3
#define GSMEM (NSTAGE * STAGE_B)      // 221184

template <int EPI, bool WF32, bool WBF>
__global__ __launch_bounds__(256, 1)
void mma_gemm(const bf16* __restrict__ Ahi, const bf16* __restrict__ Alo,
              const bf16* __restrict__ Bhi, const bf16* __restrict__ Blo,
              float* __restrict__ C, bf16* __restrict__ Chi, bf16* __restrict__ Clo,
              int M, int N, int K)
{
    extern __shared__ char sm[];
    uint32_t sb = smem_u32(sm);
    const int t = threadIdx.x, lane = t & 31, wid = t >> 5;
    const int row0 = blockIdx.y * 128, col0 = blockIdx.x * 128;

    const bf16* gA0 = Ahi + (size_t)row0 * K;
    const bf16* gA1 = Alo + (size_t)row0 * K;
    const bf16* gB0 = Bhi + (size_t)col0 * K;
    const bf16* gB1 = Blo + (size_t)col0 * K;

    const int r_ld = t >> 3, kc = t & 7;   // 32 rows x 8 16B-chunks per pass

    auto issue = [&](int s) {
        int k0 = s * BKG;
        uint32_t dst = sb + (s % NSTAGE) * STAGE_B;
        const bf16* srcs[4] = {gA0, gA1, gB0, gB1};
#pragma unroll
        for (int q = 0; q < 4; q++) {
            const bf16* base = srcs[q] + k0 + kc * 8;
            uint32_t d = dst + q * TILE_B + kc * 16;
#pragma unroll
            for (int j = 0; j < 4; j++)
                cp16(d + (r_ld + 32 * j) * RSB, base + (size_t)(r_ld + 32 * j) * K);
        }
        cp_commit();
    };

    const int wm = wid & 1, wn = wid >> 1;
    float acc[4][4][4];
#pragma unroll
    for (int i = 0; i < 4; i++)
#pragma unroll
        for (int j = 0; j < 4; j++)
#pragma unroll
            for (int r = 0; r < 4; r++) acc[i][j][r] = 0.0f;

    const int arow = wm * 64 + (lane & 15);
    const int acolh = (lane >> 4) * 16;
    const int brow = wn * 32 + (lane & 7) + ((lane >> 4) << 3);
    const int bcolh = ((lane >> 3) & 1) * 16;

    const int S = K / BKG;
    issue(0);
    issue(1);
    for (int s = 0; s < S; s++) {
        if (s + 1 < S) cp_wait<1>(); else cp_wait<0>();
        __syncthreads();
        if (s + 2 < S) issue(s + 2);

        uint32_t st = sb + (s % NSTAGE) * STAGE_B;
        uint32_t aAh = st, aAl = st + TILE_B;
        uint32_t aBh = st + 2 * TILE_B, aBl = st + 3 * TILE_B;
#pragma unroll
        for (int kb = 0; kb < 4; kb++) {
            uint32_t ah[4][4], al[4][4], bh[4][2], bl[4][2];
#pragma unroll
            for (int mi = 0; mi < 4; mi++) {
                uint32_t off = (uint32_t)(arow + mi * 16) * RSB + kb * 32 + acolh;
                ldm4(aAh + off, ah[mi][0], ah[mi][1], ah[mi][2], ah[mi][3]);
                ldm4(aAl + off, al[mi][0], al[mi][1], al[mi][2], al[mi][3]);
            }
#pragma unroll
            for (int jp = 0; jp < 2; jp++) {
                uint32_t off = (uint32_t)(brow + jp * 16) * RSB + kb * 32 + bcolh;
                uint32_t r0, r1, r2, r3;
                ldm4(aBh + off, r0, r1, r2, r3);
                bh[jp * 2][0] = r0; bh[jp * 2][1] = r1;
                bh[jp * 2 + 1][0] = r2; bh[jp * 2 + 1][1] = r3;
                ldm4(aBl + off, r0, r1, r2, r3);
                bl[jp * 2][0] = r0; bl[jp * 2][1] = r1;
                bl[jp * 2 + 1][0] = r2; bl[jp * 2 + 1][1] = r3;
            }
#pragma unroll
            for (int mi = 0; mi < 4; mi++)
#pragma unroll
                for (int nj = 0; nj < 4; nj++) {
                    mma16816(acc[mi][nj], ah[mi], bh[nj]);
                    mma16816(acc[mi][nj], ah[mi], bl[nj]);
                    mma16816(acc[mi][nj], al[mi], bh[nj]);
                }
        }
    }

    // epilogue
    const int grow = lane >> 2, gc2 = (lane & 3) * 2;
#pragma unroll
    for (int mi = 0; mi < 4; mi++) {
#pragma unroll
        for (int nj = 0; nj < 4; nj++) {
            int col = col0 + wn * 32 + nj * 8 + gc2;
#pragma unroll
            for (int h = 0; h < 2; h++) {
                size_t row = (size_t)(row0 + wm * 64 + mi * 16 + grow + h * 8);
                float v0 = acc[mi][nj][h * 2], v1 = acc[mi][nj][h * 2 + 1];
                if (EPI == 1) { v0 = siluf(v0); v1 = siluf(v1); }
                if (WF32)
                    *(float2*)&C[row * (size_t)N + col] = make_float2(v0, v1);
                if (WBF) {
                    bf16 h0, l0, h1, l1;
                    split1(v0, h0, l0);
                    split1(v1, h1, l1);
                    *(unsigned*)&Chi[row * (size_t)N + col] = packu(h0, h1);
                    *(unsigned*)&Clo[row * (size_t)N + col] = packu(l0, l1);
                }
            }
        }
    }
}

// ===================== conversion / elementwise kernels ====================

__global__ void conv_kernel(const float4* __restrict__ src,
                            bf16* __restrict__ hi, bf16* __restrict__ lo)
{
    int i = blockIdx.x * 256 + threadIdx.x;
    float4 v = src[i];
    bf16 h0, l0, h1, l1, h2, l2, h3, l3;
    split1(v.x, h0, l0); split1(v.y, h1, l1);
    split1(v.z, h2, l2); split1(v.w, h3, l3);
    ((uint2*)hi)[i] = make_uint2(packu(h0, h1), packu(h2, h3));
    ((uint2*)lo)[i] = make_uint2(packu(l0, l1), packu(l2, l3));
}

// transpose + convert: src fp32 [R][C] -> dst hi/lo bf16 [C][R]
__global__ void trans_conv_kernel(const float* __restrict__ src,
                                  bf16* __restrict__ dhi, bf16* __restrict__ dlo,
                                  int R, int C)
{
    __shared__ float tile[32][33];
    int tx = threadIdx.x, ty = threadIdx.y;   // 16 x 8
    int r0 = blockIdx.y * 32, c0 = blockIdx.x * 32;
#pragma unroll
    for (int i = 0; i < 4; i++) {
        int r = ty + i * 8;
        float2 v = *(const float2*)&src[(size_t)(r0 + r) * C + c0 + tx * 2];
        tile[r][tx * 2] = v.x;
        tile[r][tx * 2 + 1] = v.y;
    }
    __syncthreads();
#pragma unroll
    for (int i = 0; i < 4; i++) {
        int c = ty + i * 8;
        float v0 = tile[tx * 2][c], v1 = tile[tx * 2 + 1][c];
        bf16 h0, l0, h1, l1;
        split1(v0, h0, l0); split1(v1, h1, l1);
        size_t o = (size_t)(c0 + c) * R + r0 + tx * 2;
        *(unsigned*)&dhi[o] = packu(h0, h1);
        *(unsigned*)&dlo[o] = packu(l0, l1);
    }
}

// fused: ak = silu(hk); write AK hi/lo (row-major) + AKT hi/lo (transposed)
__global__ void silu_conv_trans_kernel(const float* __restrict__ src,
                                       bf16* __restrict__ hi, bf16* __restrict__ lo,
                                       bf16* __restrict__ thi, bf16* __restrict__ tlo,
                                       int R, int C)
{
    __shared__ float tile[32][33];
    int tx = threadIdx.x, ty = threadIdx.y;   // 16 x 8
    int r0 = blockIdx.y * 32, c0 = blockIdx.x * 32;
#pragma unroll
    for (int i = 0; i < 4; i++) {
        int r = ty + i * 8;
        size_t o = (size_t)(r0 + r) * C + c0 + tx * 2;
        float2 v = *(const float2*)&src[o];
        v.x = siluf(v.x); v.y = siluf(v.y);
        tile[r][tx * 2] = v.x;
        tile[r][tx * 2 + 1] = v.y;
        bf16 h0, l0, h1, l1;
        split1(v.x, h0, l0); split1(v.y, h1, l1);
        *(unsigned*)&hi[o] = packu(h0, h1);
        *(unsigned*)&lo[o] = packu(l0, l1);
    }
    __syncthreads();
#pragma unroll
    for (int i = 0; i < 4; i++) {
        int c = ty + i * 8;
        float v0 = tile[tx * 2][c], v1 = tile[tx * 2 + 1][c];
        bf16 h0, l0, h1, l1;
        split1(v0, h0, l0); split1(v1, h1, l1);
        size_t o = (size_t)(c0 + c) * R + r0 + tx * 2;
        *(unsigned*)&thi[o] = packu(h0, h1);
        *(unsigned*)&tlo[o] = packu(l0, l1);
    }
}

// fused: dp = 2*(pred - values)/(NTOK*DDIM); write DP hi/lo + DPT hi/lo
__global__ void dpred_conv_trans_kernel(const float* __restrict__ pred,
                                        const float* __restrict__ vals,
                                        bf16* __restrict__ hi, bf16* __restrict__ lo,
                                        bf16* __restrict__ thi, bf16* __restrict__ tlo,
                                        int R, int C)
{
    __shared__ float tile[32][33];
    const float cst = 2.0f / (float)((size_t)NTOK * DDIM);
    int tx = threadIdx.x, ty = threadIdx.y;   // 16 x 8
    int r0 = blockIdx.y * 32, c0 = blockIdx.x * 32;
#pragma unroll
    for (int i = 0; i < 4; i++) {
        int r = ty + i * 8;
        size_t o = (size_t)(r0 + r) * C + c0 + tx * 2;
        float2 p = *(const float2*)&pred[o];
        float2 v = *(const float2*)&vals[o];
        p.x = (p.x - v.x) * cst; p.y = (p.y - v.y) * cst;
        tile[r][tx * 2] = p.x;
        tile[r][tx * 2 + 1] = p.y;
        bf16 h0, l0, h1, l1;
        split1(p.x, h0, l0); split1(p.y, h1, l1);
        *(unsigned*)&hi[o] = packu(h0, h1);
        *(unsigned*)&lo[o] = packu(l0, l1);
    }
    __syncthreads();
#pragma unroll
    for (int i = 0; i < 4; i++) {
        int c = ty + i * 8;
        float v0 = tile[tx * 2][c], v1 = tile[tx * 2 + 1][c];
        bf16 h0, l0, h1, l1;
        split1(v0, h0, l0); split1(v1, h1, l1);
        size_t o = (size_t)(c0 + c) * R + r0 + tx * 2;
        *(unsigned*)&thi[o] = packu(h0, h1);
        *(unsigned*)&tlo[o] = packu(l0, l1);
    }
}

// fused: dh = da * silu'(hk); write only DHT hi/lo (transposed)
__global__ void dh_trans_kernel(const float* __restrict__ da,
                                const float* __restrict__ hk,
                                bf16* __restrict__ thi, bf16* __restrict__ tlo,
                                int R, int C)
{
    __shared__ float tile[32][33];
    int tx = threadIdx.x, ty = threadIdx.y;   // 16 x 8
    int r0 = blockIdx.y * 32, c0 = blockIdx.x * 32;
#pragma unroll
    for (int i = 0; i < 4; i++) {
        int r = ty + i * 8;
        size_t o = (size_t)(r0 + r) * C + c0 + tx * 2;
        float2 d = *(const float2*)&da[o];
        float2 h = *(const float2*)&hk[o];
        float s;
        s = sigf(h.x); d.x *= s * (1.0f + h.x * (1.0f - s));
        s = sigf(h.y); d.y *= s * (1.0f + h.y * (1.0f - s));
        tile[r][tx * 2] = d.x;
        tile[r][tx * 2 + 1] = d.y;
    }
    __syncthreads();
#pragma unroll
    for (int i = 0; i < 4; i++) {
        int c = ty + i * 8;
        float v0 = tile[tx * 2][c], v1 = tile[tx * 2 + 1][c];
        bf16 h0, l0, h1, l1;
        split1(v0, h0, l0); split1(v1, h1, l1);
        size_t o = (size_t)(c0 + c) * R + r0 + tx * 2;
        *(unsigned*)&thi[o] = packu(h0, h1);
        *(unsigned*)&tlo[o] = packu(l0, l1);
    }
}

template <bool WF32>
__global__ void l2norm_kernel(float* __restrict__ x,
                              bf16* __restrict__ hi, bf16* __restrict__ lo)
{
    float4* p = (float4*)(x + (size_t)blockIdx.x * DDIM);
    int t = threadIdx.x;
    float4 v = p[t];
    float ss = v.x * v.x + v.y * v.y + v.z * v.z + v.w * v.w;
    __shared__ float red[8];
#pragma unroll
    for (int o = 16; o; o >>= 1) ss += __shfl_xor_sync(~0u, ss, o);
    if ((t & 31) == 0) red[t >> 5] = ss;
    __syncthreads();
    if (t < 8) {
        float s2 = red[t];
#pragma unroll
        for (int o = 4; o; o >>= 1) s2 += __shfl_xor_sync(0xffu, s2, o);
        if (t == 0) red[0] = s2;
    }
    __syncthreads();
    float scale = 1.0f / fmaxf(sqrtf(red[0]), 1e-12f);
    v.x *= scale; v.y *= scale; v.z *= scale; v.w *= scale;
    if (WF32) p[t] = v;
    size_t i = (size_t)blockIdx.x * 256 + t;
    bf16 h0, l0, h1, l1, h2, l2, h3, l3;
    split1(v.x, h0, l0); split1(v.y, h1, l1);
    split1(v.z, h2, l2); split1(v.w, h3, l3);
    ((uint2*)hi)[i] = make_uint2(packu(h0, h1), packu(h2, h3));
    ((uint2*)lo)[i] = make_uint2(packu(l0, l1), packu(l2, l3));
}

__global__ void xmean_kernel(const float* __restrict__ x, float* __restrict__ xm)
{
    int idx = blockIdx.x * 256 + threadIdx.x;
    int b = idx >> 10, d = idx & 1023;
    const float* p = x + ((size_t)b * 2048) * DDIM + d;
    float s = 0.0f;
#pragma unroll 8
    for (int ss = 0; ss < 2048; ss++) s += p[(size_t)ss * DDIM];
    xm[idx] = s * (1.0f / 2048.0f);
}

__global__ void gate_partial_kernel(
    const float* __restrict__ xm,
    const float* __restrict__ gdw, const float* __restrict__ gdb,
    const float* __restrict__ glw, const float* __restrict__ glb,
    const float* __restrict__ gmw, const float* __restrict__ gmb,
    float* __restrict__ part)
{
    int g = blockIdx.y;
    const float* W = (g == 0) ? gdw : (g == 1) ? glw : gmw;
    const float* bias = (g == 0) ? gdb : (g == 1) ? glb : gmb;
    int warp = threadIdx.x >> 5, lane = threadIdx.x & 31;
    float acc = 0.0f;
#pragma unroll
    for (int jj = 0; jj < 8; jj++) {
        int j = blockIdx.x * 32 + warp * 8 + jj;
        const float* wr = W + (size_t)j * DDIM;
        float bj = bias[j];
        for (int bb = 0; bb < 4; bb++) {
            const float* xr = xm + bb * DDIM;
            float s = 0.0f;
            for (int d = lane; d < DDIM; d += 32) s += xr[d] * wr[d];
#pragma unroll
            for (int o = 16; o; o >>= 1) s += __shfl_xor_sync(~0u, s, o);
            if (lane == 0) acc += sigf(s + bj);
        }
    }
    __shared__ float sred[4];
    if (lane == 0) sred[warp] = acc;
    __syncthreads();
    if (threadIdx.x == 0)
        part[g * 32 + blockIdx.x] = sred[0] + sred[1] + sred[2] + sred[3];
}

__global__ void gate_final_kernel(const float* __restrict__ part, float* __restrict__ gates)
{
    int t = threadIdx.x;
    if (t < 96) {
        int g = t >> 5, lane = t & 31;
        float v = part[g * 32 + lane];
#pragma unroll
        for (int o = 16; o; o >>= 1) v += __shfl_xor_sync(~0u, v, o);
        if (lane == 0) gates[g] = v * (1.0f / 4096.0f);
    }
}

__global__ void update_kernel(
    const float4* __restrict__ w0, const float4* __restrict__ w1,
    const float4* __restrict__ m0, const float4* __restrict__ m1,
    const float4* __restrict__ gg0, const float4* __restrict__ gg1,
    const float* __restrict__ gates, float4* __restrict__ out4)
{
    const int HD4 = HDIM * DDIM / 4;
    int i = blockIdx.x * 256 + threadIdx.x;
    float alpha = gates[0], theta = gates[1], eta = gates[2];
    float oma = 1.0f - alpha;
    if (i < HD4) {
        float4 g = gg0[i], m = m0[i], w = w0[i], nm, nw;
        nm.x = eta * m.x - theta * g.x; nw.x = oma * w.x + nm.x;
        nm.y = eta * m.y - theta * g.y; nw.y = oma * w.y + nm.y;
        nm.z = eta * m.z - theta * g.z; nw.z = oma * w.z + nm.z;
        nm.w = eta * m.w - theta * g.w; nw.w = oma * w.w + nm.w;
        out4[2097152 + i] = nw;
        out4[3145728 + i] = nm;
    } else {
        int j = i - HD4;
        float4 g = gg1[j], m = m1[j], w = w1[j], nm, nw;
        nm.x = eta * m.x - theta * g.x; nw.x = oma * w.x + nm.x;
        nm.y = eta * m.y - theta * g.y; nw.y = oma * w.y + nm.y;
        nm.z = eta * m.z - theta * g.z; nw.z = oma * w.z + nm.z;
        nm.w = eta * m.w - theta * g.w; nw.w = oma * w.w + nm.w;
        out4[2621440 + j] = nw;
        out4[3670016 + j] = nm;
    }
}

// ===================== host ================================================

extern "C" void kernel_launch(void* const* d_in, const int* in_sizes, int n_in,
                              void* d_out, int out_size)
{
    (void)in_sizes; (void)n_in; (void)out_size;
    const float* x      = (const float*)d_in[0];
    const float* kp_w1  = (const float*)d_in[1];
    const float* kp_w2  = (const float*)d_in[2];
    const float* vp_w1  = (const float*)d_in[3];
    const float* vp_w2  = (const float*)d_in[4];
    const float* qp_w1  = (const float*)d_in[5];
    const float* qp_w2  = (const float*)d_in[6];
    const float* gd_w   = (const float*)d_in[7];
    const float* gd_b   = (const float*)d_in[8];
    const float* gl_w   = (const float*)d_in[9];
    const float* gl_b   = (const float*)d_in[10];
    const float* gm_w   = (const float*)d_in[11];
    const float* gm_b   = (const float*)d_in[12];
    const float* mem_w0 = (const float*)d_in[13];
    const float* mem_w1 = (const float*)d_in[14];
    const float* mom0   = (const float*)d_in[15];
    const float* mom1   = (const float*)d_in[16];
    const float* out_w  = (const float*)d_in[17];
    float* out = (float*)d_out;

    float *keys, *values, *queries, *hk, *pred, *da, *gg0, *gg1;
    float *xmean, *gpart, *gates;
    bf16 *bh, *bl;
    cudaGetSymbolAddress((void**)&keys, g_keys);
    cudaGetSymbolAddress((void**)&values, g_values);
    cudaGetSymbolAddress((void**)&queries, g_queries);
    cudaGetSymbolAddress((void**)&hk, g_hk);
    cudaGetSymbolAddress((void**)&pred, g_pred);
    cudaGetSymbolAddress((void**)&da, g_da);
    cudaGetSymbolAddress((void**)&gg0, g_g0);
    cudaGetSymbolAddress((void**)&gg1, g_g1);
    cudaGetSymbolAddress((void**)&xmean, g_xmean);
    cudaGetSymbolAddress((void**)&gpart, g_gpart);
    cudaGetSymbolAddress((void**)&gates, g_gates);
    cudaGetSymbolAddress((void**)&bh, g_bfh);
    cudaGetSymbolAddress((void**)&bl, g_bfl);

    cudaFuncSetAttribute(mma_gemm<1, false, true>, cudaFuncAttributeMaxDynamicSharedMemorySize, GSMEM);
    cudaFuncSetAttribute(mma_gemm<1, true, false>, cudaFuncAttributeMaxDynamicSharedMemorySize, GSMEM);
    cudaFuncSetAttribute(mma_gemm<0, false, true>, cudaFuncAttributeMaxDynamicSharedMemorySize, GSMEM);
    cudaFuncSetAttribute(mma_gemm<0, true, false>, cudaFuncAttributeMaxDynamicSharedMemorySize, GSMEM);

    // ---- gates (independent chain) ----
    xmean_kernel<<<16, 256>>>(x, xmean);
    gate_partial_kernel<<<dim3(32, 3), 128>>>(xmean, gd_w, gd_b, gl_w, gl_b,
                                              gm_w, gm_b, gpart);
    gate_final_kernel<<<1, 96>>>(gpart, gates);

    // ---- conversions of inputs ----
    conv_kernel<<<8192, 256>>>((const float4*)x, bh + O_X, bl + O_X);
    conv_kernel<<<1024, 256>>>((const float4*)kp_w1, bh + O_KP1, bl + O_KP1);
    conv_kernel<<<1024, 256>>>((const float4*)kp_w2, bh + O_KP2, bl + O_KP2);
    conv_kernel<<<1024, 256>>>((const float4*)vp_w1, bh + O_VP1, bl + O_VP1);
    conv_kernel<<<1024, 256>>>((const float4*)vp_w2, bh + O_VP2, bl + O_VP2);
    conv_kernel<<<1024, 256>>>((const float4*)qp_w1, bh + O_QP1, bl + O_QP1);
    conv_kernel<<<1024, 256>>>((const float4*)qp_w2, bh + O_QP2, bl + O_QP2);
    conv_kernel<<<1024, 256>>>((const float4*)out_w, bh + O_OW, bl + O_OW);
    conv_kernel<<<2048, 256>>>((const float4*)mem_w0, bh + O_M0, bl + O_M0);
    conv_kernel<<<2048, 256>>>((const float4*)mem_w1, bh + O_M1, bl + O_M1);
    trans_conv_kernel<<<dim3(HDIM / 32, DDIM / 32), dim3(16, 8)>>>(
        mem_w1, bh + O_M1T, bl + O_M1T, DDIM, HDIM);   // w1T [H][D]

    dim3 blk(256);
    dim3 ttb(16, 8);
    dim3 gND(DDIM / 128, NTOK / 128);   // (8, 64)
    dim3 gNH(HDIM / 128, NTOK / 128);   // (16, 64)

    // ---- K projection ----
    mma_gemm<1, false, true><<<gND, blk, GSMEM>>>(
        bh + O_X, bl + O_X, bh + O_KP1, bl + O_KP1,
        nullptr, bh + O_T1, bl + O_T1, NTOK, DDIM, DDIM);
    mma_gemm<1, true, false><<<gND, blk, GSMEM>>>(
        bh + O_T1, bl + O_T1, bh + O_KP2, bl + O_KP2,
        keys, nullptr, nullptr, NTOK, DDIM, DDIM);
    l2norm_kernel<true><<<NTOK, 256>>>(keys, bh + O_KEY, bl + O_KEY);
    trans_conv_kernel<<<dim3(DDIM / 32, NTOK / 32), ttb>>>(
        keys, bh + O_KEYT, bl + O_KEYT, NTOK, DDIM);   // keysT [D][NTOK]

    // ---- V projection ----
    mma_gemm<1, false, true><<<gND, blk, GSMEM>>>(
        bh + O_X, bl + O_X, bh + O_VP1, bl + O_VP1,
        nullptr, bh + O_T1, bl + O_T1, NTOK, DDIM, DDIM);
    mma_gemm<1, true, false><<<gND, blk, GSMEM>>>(
        bh + O_T1, bl + O_T1, bh + O_VP2, bl + O_VP2,
        values, nullptr, nullptr, NTOK, DDIM, DDIM);

    // ---- Q projection ----
    mma_gemm<1, false, true><<<gND, blk, GSMEM>>>(
        bh + O_X, bl + O_X, bh + O_QP1, bl + O_QP1,
        nullptr, bh + O_T1, bl + O_T1, NTOK, DDIM, DDIM);
    mma_gemm<1, true, false><<<gND, blk, GSMEM>>>(
        bh + O_T1, bl + O_T1, bh + O_QP2, bl + O_QP2,
        queries, nullptr, nullptr, NTOK, DDIM, DDIM);
    l2norm_kernel<false><<<NTOK, 256>>>(queries, bh + O_Q, bl + O_Q);

    // ---- memory read: retr = silu(q @ w0^T) @ w1^T ; out = retr @ out_w^T ----
    mma_gemm<1, false, true><<<gNH, blk, GSMEM>>>(
        bh + O_Q, bl + O_Q, bh + O_M0, bl + O_M0,
        nullptr, bh + O_AQ, bl + O_AQ, NTOK, HDIM, DDIM);
    mma_gemm<0, false, true><<<gND, blk, GSMEM>>>(
        bh + O_AQ, bl + O_AQ, bh + O_M1, bl + O_M1,
        nullptr, bh + O_RETR, bl + O_RETR, NTOK, DDIM, HDIM);
    mma_gemm<0, true, false><<<gND, blk, GSMEM>>>(
        bh + O_RETR, bl + O_RETR, bh + O_OW, bl + O_OW,
        out, nullptr, nullptr, NTOK, DDIM, DDIM);

    // ---- loss forward on keys ----
    mma_gemm<0, true, false><<<gNH, blk, GSMEM>>>(
        bh + O_KEY, bl + O_KEY, bh + O_M0, bl + O_M0,
        hk, nullptr, nullptr, NTOK, HDIM, DDIM);
    silu_conv_trans_kernel<<<dim3(HDIM / 32, NTOK / 32), ttb>>>(
        hk, bh + O_AK, bl + O_AK, bh + O_AKT, bl + O_AKT, NTOK, HDIM);
    mma_gemm<0, true, false><<<gND, blk, GSMEM>>>(
        bh + O_AK, bl + O_AK, bh + O_M1, bl + O_M1,
        pred, nullptr, nullptr, NTOK, DDIM, HDIM);
    dpred_conv_trans_kernel<<<dim3(DDIM / 32, NTOK / 32), ttb>>>(
        pred, values, bh + O_DP, bl + O_DP, bh + O_DPT, bl + O_DPT, NTOK, DDIM);

    // ---- backward ----
    // g1[D,H] = dpredT . akT   (K = NTOK)
    mma_gemm<0, true, false><<<dim3(HDIM / 128, DDIM / 128), blk, GSMEM>>>(
        bh + O_DPT, bl + O_DPT, bh + O_AKT, bl + O_AKT,
        gg1, nullptr, nullptr, DDIM, HDIM, NTOK);
    // da[N,H] = dpred . w1T    (K = D)
    mma_gemm<0, true, false><<<gNH, blk, GSMEM>>>(
        bh + O_DP, bl + O_DP, bh + O_M1T, bl + O_M1T,
        da, nullptr, nullptr, NTOK, HDIM, DDIM);
    dh_trans_kernel<<<dim3(HDIM / 32, NTOK / 32), ttb>>>(
        da, hk, bh + O_DHT, bl + O_DHT, NTOK, HDIM);
    // g0[H,D] = dhT . keysT    (K = NTOK)
    mma_gemm<0, true, false><<<dim3(DDIM / 128, HDIM / 128), blk, GSMEM>>>(
        bh + O_DHT, bl + O_DHT, bh + O_KEYT, bl + O_KEYT,
        gg0, nullptr, nullptr, HDIM, DDIM, NTOK);

    // ---- weight / momentum update ----
    update_kernel<<<2 * HDIM * DDIM / 4 / 256, 256>>>(
        (const float4*)mem_w0, (const float4*)mem_w1,
        (const float4*)mom0, (const float4*)mom1,
        (const float4*)gg0, (const float4*)gg1, gates, (float4*)out);
}